// round 9
// baseline (speedup 1.0000x reference)
#include <cuda_runtime.h>
#include <cstdint>

// Problem constants
#define NN      8192
#define CH      16
#define KT      256            // k staged per half per iteration
#define NIT     16             // staging iterations (16 * 256 * 2 halves = 8192)
#define RS      (2 * KT + 4)   // 516 floats per (q,c2) shared row (16B-aligned, bank-staggered)
#define THREADS 128
#define RPC     16             // rows per CTA
#define NCTA    (NN / RPC)     // 512

// Scratch (no allocation allowed): ping-pong xp buffers + accumulator
__device__ __align__(128) float g_xbuf0[NN * CH];
__device__ __align__(128) float g_xbuf1[NN * CH];
__device__ __align__(128) float g_acc[NN * CH];

// ---------------- packed f32x2 helpers ----------------
__device__ __forceinline__ unsigned long long f2_fma(unsigned long long a,
                                                     unsigned long long b,
                                                     unsigned long long c) {
    unsigned long long d;
    asm("fma.rn.f32x2 %0, %1, %2, %3;" : "=l"(d) : "l"(a), "l"(b), "l"(c));
    return d;
}
__device__ __forceinline__ unsigned long long f2_add(unsigned long long a,
                                                     unsigned long long b) {
    unsigned long long d;
    asm("add.rn.f32x2 %0, %1, %2;" : "=l"(d) : "l"(a), "l"(b));
    return d;
}
__device__ __forceinline__ unsigned long long f2_pack(float lo, float hi) {
    unsigned long long d;
    asm("mov.b64 %0, {%1, %2};" : "=l"(d) : "f"(lo), "f"(hi));
    return d;
}
__device__ __forceinline__ void f2_unpack(unsigned long long v, float& lo, float& hi) {
    asm("mov.b64 {%0, %1}, %2;" : "=f"(lo), "=f"(hi) : "l"(v));
}

// ---------------- kernel 0: acc = relu(x @ W0) ----------------
__global__ void k_init(const float* __restrict__ x,
                       const float* __restrict__ W,   // W0: [16][16]
                       float* __restrict__ acc) {
    __shared__ float sW[CH * CH];
    int t = threadIdx.x;
    sW[t] = W[t];
    __syncthreads();

    int row = blockIdx.x * blockDim.x + t;
    const float4* xr4 = reinterpret_cast<const float4*>(x + (size_t)row * CH);
    float xr[CH];
    float4 v0 = xr4[0], v1 = xr4[1], v2 = xr4[2], v3 = xr4[3];
    xr[0]=v0.x; xr[1]=v0.y; xr[2]=v0.z; xr[3]=v0.w;
    xr[4]=v1.x; xr[5]=v1.y; xr[6]=v1.z; xr[7]=v1.w;
    xr[8]=v2.x; xr[9]=v2.y; xr[10]=v2.z; xr[11]=v2.w;
    xr[12]=v3.x; xr[13]=v3.y; xr[14]=v3.z; xr[15]=v3.w;

    float o[CH];
    #pragma unroll
    for (int c = 0; c < CH; c++) o[c] = 0.f;
    #pragma unroll
    for (int j = 0; j < CH; j++) {
        #pragma unroll
        for (int c = 0; c < CH; c++) o[c] += xr[j] * sW[j * CH + c];
    }
    float* ar = acc + (size_t)row * CH;
    #pragma unroll
    for (int c = 0; c < CH; c++) ar[c] = fmaxf(o[c], 0.f);
}

// ---------------- pass kernel ----------------
// 4 warps/CTA: warp = q (k half, bit 1) x s (rowset of 8, bit 0).
// Lane = h*16 + j: half-warps h=0/1 handle interleaved rows 2r+h (r=0..3),
// j strides k (2 floats per lane, 32 k per step). LDG.64 => 2 full 128B lines.
// LDS.128 => 16 unique addrs (2 phases) broadcast across h.
template <bool FINAL>
__global__ __launch_bounds__(THREADS, 4)
void k_pass(const float* __restrict__ L,
            const float* __restrict__ xin,
            float* __restrict__ xout,
            const float* __restrict__ W,      // Wp: [16][16]
            float* __restrict__ acc,
            float* __restrict__ outp) {
    // sxp[q][c2][2*k + e]: pair-major transposed xp chunk, per k-half q
    __shared__ __align__(16) float sxp[2 * 8 * RS];
    __shared__ float sW[CH * CH];

    int t = threadIdx.x;
    sW[t] = W[t];
    sW[t + 128] = W[t + 128];

    int warp = t >> 5;
    int lane = t & 31;
    int q = warp >> 1;          // k half (0: k<4096, 1: k>=4096)
    int s = warp & 1;           // rowset (8 rows)
    int h = lane >> 4;          // row parity within warp
    int j = lane & 15;          // k lane

    int ctarow = blockIdx.x * RPC;
    const float* Lb = L + (size_t)(ctarow + s * 8 + h) * NN + q * (NN / 2);
    const float4* xin4 = reinterpret_cast<const float4*>(xin);

    unsigned long long a2[4][8];
    #pragma unroll
    for (int r = 0; r < 4; r++)
        #pragma unroll
        for (int c2 = 0; c2 < 8; c2++) a2[r][c2] = 0ull;

    for (int i = 0; i < NIT; i++) {
        // ---- stage 256 k per half into pair-major transposed shared ----
        #pragma unroll
        for (int jj = 0; jj < 16; jj++) {
            int idx4 = jj * THREADS + t;          // 0..2047
            int k  = idx4 >> 2;                   // 0..511
            int c4 = idx4 & 3;
            int q0 = k >> 8;                      // which half
            int kl = k & 255;
            int kg = q0 * (NN / 2) + i * KT + kl; // global k row of xin
            float4 v = xin4[(size_t)kg * 4 + c4];
            float* d = sxp + q0 * 8 * RS + 2 * kl;
            *reinterpret_cast<float2*>(d + (2 * c4    ) * RS) = make_float2(v.x, v.y);
            *reinterpret_cast<float2*>(d + (2 * c4 + 1) * RS) = make_float2(v.z, v.w);
        }
        __syncthreads();

        const float* Lc = Lb + i * KT;
        const float* sx = sxp + q * 8 * RS;
        #pragma unroll 4
        for (int it = 0; it < 8; ++it) {          // 8 steps of 32 k
            int kb = it * 32 + 2 * j;
            float2 lv0 = *(const float2*)(Lc + 0 * NN + kb);
            float2 lv1 = *(const float2*)(Lc + 2 * NN + kb);
            float2 lv2 = *(const float2*)(Lc + 4 * NN + kb);
            float2 lv3 = *(const float2*)(Lc + 6 * NN + kb);
            unsigned long long x0 = f2_pack(lv0.x, lv0.x), y0 = f2_pack(lv0.y, lv0.y);
            unsigned long long x1 = f2_pack(lv1.x, lv1.x), y1 = f2_pack(lv1.y, lv1.y);
            unsigned long long x2 = f2_pack(lv2.x, lv2.x), y2 = f2_pack(lv2.y, lv2.y);
            unsigned long long x3 = f2_pack(lv3.x, lv3.x), y3 = f2_pack(lv3.y, lv3.y);
            const float* bp = sx + 2 * kb;
            #pragma unroll
            for (int c2 = 0; c2 < 8; c2++) {
                ulonglong2 qv = *reinterpret_cast<const ulonglong2*>(bp + c2 * RS);
                a2[0][c2] = f2_fma(x0, qv.x, a2[0][c2]);
                a2[0][c2] = f2_fma(y0, qv.y, a2[0][c2]);
                a2[1][c2] = f2_fma(x1, qv.x, a2[1][c2]);
                a2[1][c2] = f2_fma(y1, qv.y, a2[1][c2]);
                a2[2][c2] = f2_fma(x2, qv.x, a2[2][c2]);
                a2[2][c2] = f2_fma(y2, qv.y, a2[2][c2]);
                a2[3][c2] = f2_fma(x3, qv.x, a2[3][c2]);
                a2[3][c2] = f2_fma(y3, qv.y, a2[3][c2]);
            }
        }
        __syncthreads();
    }

    // ---- reduce over j lanes (xor 1,2,4,8 keeps h groups separate) ----
    float y[4][CH];
    #pragma unroll
    for (int r = 0; r < 4; r++) {
        #pragma unroll
        for (int c2 = 0; c2 < 8; c2++) {
            unsigned long long v = a2[r][c2];
            v = f2_add(v, __shfl_xor_sync(0xffffffffu, v, 1, 32));
            v = f2_add(v, __shfl_xor_sync(0xffffffffu, v, 2, 32));
            v = f2_add(v, __shfl_xor_sync(0xffffffffu, v, 4, 32));
            v = f2_add(v, __shfl_xor_sync(0xffffffffu, v, 8, 32));
            f2_unpack(v, y[r][2 * c2], y[r][2 * c2 + 1]);
        }
    }

    // ---- cross-half combine via shared (reuse sxp; synced above) ----
    // red[warp][rowlocal(0..7)*16 + ch]; warp = q*2 + s
    float* red = sxp;
    #pragma unroll
    for (int r = 0; r < 4; r++)
        red[warp * 128 + (2 * r + h) * 16 + j] = y[r][j];
    __syncthreads();

    float* redsum = sxp + 512;
    #pragma unroll
    for (int hh = 0; hh < 2; hh++) {
        int o = t + hh * 128;          // 0..255 = rowlocal*16 + ch
        int rl = o >> 4, c = o & 15;
        int s2 = rl >> 3, rr = rl & 7;
        float ys = red[(0 * 2 + s2) * 128 + rr * 16 + c]
                 + red[(1 * 2 + s2) * 128 + rr * 16 + c];
        redsum[o] = ys;
        if (!FINAL)
            xout[(size_t)(ctarow + rl) * CH + c] = ys;   // raw L^p x
    }
    __syncthreads();

    // ---- tiny GEMM with Wp + relu + accumulate ----
    #pragma unroll
    for (int hh = 0; hh < 2; hh++) {
        int o = t + hh * 128;
        int rl = o >> 4, c = o & 15;
        float sv = 0.f;
        #pragma unroll
        for (int jj = 0; jj < CH; jj++) sv += redsum[rl * 16 + jj] * sW[jj * CH + c];
        sv = fmaxf(sv, 0.f);
        size_t gi = (size_t)(ctarow + rl) * CH + c;
        if (!FINAL) {
            acc[gi] += sv;
        } else {
            outp[gi] = fmaxf(acc[gi] + sv, 0.f);
        }
    }
}

extern "C" void kernel_launch(void* const* d_in, const int* in_sizes, int n_in,
                              void* d_out, int out_size) {
    const float* x = (const float*)d_in[0];   // [8192, 16]
    const float* L = (const float*)d_in[1];   // [8192, 8192]
    const float* W = (const float*)d_in[2];   // [5, 16, 16]
    float* out = (float*)d_out;

    void *p0, *p1, *pa;
    cudaGetSymbolAddress(&p0, g_xbuf0);
    cudaGetSymbolAddress(&p1, g_xbuf1);
    cudaGetSymbolAddress(&pa, g_acc);
    float* xb0 = (float*)p0;
    float* xb1 = (float*)p1;
    float* acc = (float*)pa;

    k_init<<<NN / 256, 256>>>(x, W, acc);                                     // acc = relu(x@W0)
    k_pass<false><<<NCTA, THREADS>>>(L, x,   xb0, W + 1 * 256, acc, nullptr); // p=1
    k_pass<false><<<NCTA, THREADS>>>(L, xb0, xb1, W + 2 * 256, acc, nullptr); // p=2
    k_pass<false><<<NCTA, THREADS>>>(L, xb1, xb0, W + 3 * 256, acc, nullptr); // p=3
    k_pass<true ><<<NCTA, THREADS>>>(L, xb0, nullptr, W + 4 * 256, acc, out); // p=4
}

// round 10
// speedup vs baseline: 1.1641x; 1.1641x over previous
#include <cuda_runtime.h>
#include <cstdint>

// Problem constants
#define NN      8192
#define CH      16
#define KT      512            // k per chunk staged in shared
#define RS      1028           // padded floats per channel-pair row (2*KT + 4)
#define SEG     512            // seg1 offset within a row (even/odd k-pair split)
#define RPW     4              // rows per warp
#define RPC     32             // rows per CTA
#define THREADS 256
#define NCTA    (NN / RPC)     // 256

// Scratch (no allocation allowed): ping-pong xp buffers + accumulator
__device__ __align__(128) float g_xbuf0[NN * CH];
__device__ __align__(128) float g_xbuf1[NN * CH];
__device__ __align__(128) float g_acc[NN * CH];

// ---------------- packed f32x2 helpers ----------------
__device__ __forceinline__ unsigned long long f2_fma(unsigned long long a,
                                                     unsigned long long b,
                                                     unsigned long long c) {
    unsigned long long d;
    asm("fma.rn.f32x2 %0, %1, %2, %3;" : "=l"(d) : "l"(a), "l"(b), "l"(c));
    return d;
}
__device__ __forceinline__ unsigned long long f2_add(unsigned long long a,
                                                     unsigned long long b) {
    unsigned long long d;
    asm("add.rn.f32x2 %0, %1, %2;" : "=l"(d) : "l"(a), "l"(b));
    return d;
}
__device__ __forceinline__ unsigned long long f2_pack(float lo, float hi) {
    unsigned long long d;
    asm("mov.b64 %0, {%1, %2};" : "=l"(d) : "f"(lo), "f"(hi));
    return d;
}
__device__ __forceinline__ void f2_unpack(unsigned long long v, float& lo, float& hi) {
    asm("mov.b64 {%0, %1}, %2;" : "=f"(lo), "=f"(hi) : "l"(v));
}

// ---------------- kernel 0: acc = relu(x @ W0) ----------------
__global__ void k_init(const float* __restrict__ x,
                       const float* __restrict__ W,   // W0: [16][16]
                       float* __restrict__ acc) {
    __shared__ float sW[CH * CH];
    int t = threadIdx.x;
    sW[t] = W[t];
    __syncthreads();

    int row = blockIdx.x * blockDim.x + t;
    const float4* xr4 = reinterpret_cast<const float4*>(x + (size_t)row * CH);
    float xr[CH];
    float4 v0 = xr4[0], v1 = xr4[1], v2 = xr4[2], v3 = xr4[3];
    xr[0]=v0.x; xr[1]=v0.y; xr[2]=v0.z; xr[3]=v0.w;
    xr[4]=v1.x; xr[5]=v1.y; xr[6]=v1.z; xr[7]=v1.w;
    xr[8]=v2.x; xr[9]=v2.y; xr[10]=v2.z; xr[11]=v2.w;
    xr[12]=v3.x; xr[13]=v3.y; xr[14]=v3.z; xr[15]=v3.w;

    float o[CH];
    #pragma unroll
    for (int c = 0; c < CH; c++) o[c] = 0.f;
    #pragma unroll
    for (int j = 0; j < CH; j++) {
        #pragma unroll
        for (int c = 0; c < CH; c++) o[c] += xr[j] * sW[j * CH + c];
    }
    float* ar = acc + (size_t)row * CH;
    #pragma unroll
    for (int c = 0; c < CH; c++) ar[c] = fmaxf(o[c], 0.f);
}

// ---------------- pass kernel (r3 skeleton, k-stride-4 inner loop) ----------------
// 8 warps/CTA, warp owns 4 contiguous rows, full-k sweep.
// Lane j covers k = 4j..4j+3 per 128-k step via LDG.128 on L.
// Shared seg layout per channel pair c2:
//   seg0 (floats [0,512)):   k-pairs with k%4 in {0,1}: quad qd at 4*qd holds
//                            (xp[K][2c2], xp[K][2c2+1], xp[K+1][2c2], xp[K+1][2c2+1]), K=4*qd
//   seg1 (floats [512,1024)): same for K=4*qd+2
// Compute LDS.128 at c2*RS + kb (and +SEG), lanes at 16B stride: conflict-free.
template <bool FINAL>
__global__ __launch_bounds__(THREADS, 2)
void k_pass(const float* __restrict__ L,
            const float* __restrict__ xin,
            float* __restrict__ xout,
            const float* __restrict__ W,      // Wp: [16][16]
            float* __restrict__ acc,
            float* __restrict__ outp) {
    __shared__ __align__(16) float sxp[8 * RS];
    __shared__ float sW[CH * CH];

    int t = threadIdx.x;
    sW[t] = W[t];

    int warp = t >> 5;
    int lane = t & 31;
    int rowbase = blockIdx.x * RPC + warp * RPW;
    const float* Lr = L + (size_t)rowbase * NN;

    unsigned long long a2[RPW][8];
    #pragma unroll
    for (int r = 0; r < RPW; r++)
        #pragma unroll
        for (int c2 = 0; c2 < 8; c2++) a2[r][c2] = 0ull;

    for (int chunk = 0; chunk < NN / KT; ++chunk) {   // 16 chunks
        // ---- stage xp chunk into segmented pair-major shared ----
        const float4* xin4 = reinterpret_cast<const float4*>(xin + (size_t)chunk * KT * CH);
        #pragma unroll
        for (int jj = 0; jj < (KT * CH / 4) / THREADS; jj++) {   // 8 iters
            int idx4 = jj * THREADS + t;          // 0..2047
            float4 v = xin4[idx4];
            int k  = idx4 >> 2;                   // 0..511
            int c4 = idx4 & 3;                    // channel group (4 channels)
            int pos = 4 * (k >> 2) + 2 * (k & 1) + ((k >> 1) & 1) * SEG;
            *reinterpret_cast<float2*>(&sxp[(2 * c4    ) * RS + pos]) = make_float2(v.x, v.y);
            *reinterpret_cast<float2*>(&sxp[(2 * c4 + 1) * RS + pos]) = make_float2(v.z, v.w);
        }
        __syncthreads();

        const float* Lc = Lr + chunk * KT;
        #pragma unroll 2
        for (int it = 0; it < KT / 128; ++it) {   // 4 steps of 128 k
            int kb = it * 128 + 4 * lane;

            float4 lv0 = *reinterpret_cast<const float4*>(Lc + 0 * NN + kb);
            float4 lv1 = *reinterpret_cast<const float4*>(Lc + 1 * NN + kb);
            float4 lv2 = *reinterpret_cast<const float4*>(Lc + 2 * NN + kb);
            float4 lv3 = *reinterpret_cast<const float4*>(Lc + 3 * NN + kb);

            unsigned long long p0[RPW], p1[RPW], p2[RPW], p3[RPW];
            p0[0]=f2_pack(lv0.x,lv0.x); p1[0]=f2_pack(lv0.y,lv0.y); p2[0]=f2_pack(lv0.z,lv0.z); p3[0]=f2_pack(lv0.w,lv0.w);
            p0[1]=f2_pack(lv1.x,lv1.x); p1[1]=f2_pack(lv1.y,lv1.y); p2[1]=f2_pack(lv1.z,lv1.z); p3[1]=f2_pack(lv1.w,lv1.w);
            p0[2]=f2_pack(lv2.x,lv2.x); p1[2]=f2_pack(lv2.y,lv2.y); p2[2]=f2_pack(lv2.z,lv2.z); p3[2]=f2_pack(lv2.w,lv2.w);
            p0[3]=f2_pack(lv3.x,lv3.x); p1[3]=f2_pack(lv3.y,lv3.y); p2[3]=f2_pack(lv3.z,lv3.z); p3[3]=f2_pack(lv3.w,lv3.w);

            #pragma unroll
            for (int c2 = 0; c2 < 8; c2++) {
                ulonglong2 q0 = *reinterpret_cast<const ulonglong2*>(&sxp[c2 * RS + kb]);        // k, k+1
                ulonglong2 q1 = *reinterpret_cast<const ulonglong2*>(&sxp[c2 * RS + SEG + kb]);  // k+2, k+3
                #pragma unroll
                for (int r = 0; r < RPW; r++) {
                    a2[r][c2] = f2_fma(p0[r], q0.x, a2[r][c2]);
                    a2[r][c2] = f2_fma(p1[r], q0.y, a2[r][c2]);
                    a2[r][c2] = f2_fma(p2[r], q1.x, a2[r][c2]);
                    a2[r][c2] = f2_fma(p3[r], q1.y, a2[r][c2]);
                }
            }
        }
        __syncthreads();
    }

    // ---- warp butterfly reduction: every lane ends with full y[4][16] ----
    float y[RPW][CH];
    #pragma unroll
    for (int r = 0; r < RPW; r++) {
        #pragma unroll
        for (int c2 = 0; c2 < 8; c2++) {
            unsigned long long v = a2[r][c2];
            #pragma unroll
            for (int off = 16; off > 0; off >>= 1)
                v = f2_add(v, __shfl_xor_sync(0xffffffffu, v, off, 32));
            f2_unpack(v, y[r][2 * c2], y[r][2 * c2 + 1]);
        }
    }

    // ---- epilogue: each lane produces 2 of the 64 (row, channel) outputs ----
    #pragma unroll
    for (int h = 0; h < 2; ++h) {
        int o = lane + h * 32;
        int r = o >> 4;
        int c = o & 15;
        float s = 0.f;
        #pragma unroll
        for (int j = 0; j < CH; j++) s += y[r][j] * sW[j * CH + c];
        s = fmaxf(s, 0.f);                       // relu(y @ Wp)
        size_t gi = (size_t)(rowbase + r) * CH + c;
        if (!FINAL) {
            acc[gi] += s;
            xout[gi] = y[r][c];                  // raw L^p x for next pass
        } else {
            outp[gi] = fmaxf(acc[gi] + s, 0.f);  // final relu
        }
    }
}

extern "C" void kernel_launch(void* const* d_in, const int* in_sizes, int n_in,
                              void* d_out, int out_size) {
    const float* x = (const float*)d_in[0];   // [8192, 16]
    const float* L = (const float*)d_in[1];   // [8192, 8192]
    const float* W = (const float*)d_in[2];   // [5, 16, 16]
    float* out = (float*)d_out;

    void *p0, *p1, *pa;
    cudaGetSymbolAddress(&p0, g_xbuf0);
    cudaGetSymbolAddress(&p1, g_xbuf1);
    cudaGetSymbolAddress(&pa, g_acc);
    float* xb0 = (float*)p0;
    float* xb1 = (float*)p1;
    float* acc = (float*)pa;

    k_init<<<NN / THREADS, THREADS>>>(x, W, acc);                                   // acc = relu(x@W0)
    k_pass<false><<<NCTA, THREADS>>>(L, x,   xb0, W + 1 * 256, acc, nullptr);       // p=1
    k_pass<false><<<NCTA, THREADS>>>(L, xb0, xb1, W + 2 * 256, acc, nullptr);       // p=2
    k_pass<false><<<NCTA, THREADS>>>(L, xb1, xb0, W + 3 * 256, acc, nullptr);       // p=3
    k_pass<true ><<<NCTA, THREADS>>>(L, xb0, nullptr, W + 4 * 256, acc, out);       // p=4 + final relu
}

// round 13
// speedup vs baseline: 1.8183x; 1.5620x over previous
#include <cuda_runtime.h>
#include <cuda_bf16.h>
#include <cstdint>

// Problem constants
#define NN       8192
#define CH       16
#define KSPLIT   8
#define KRANGE   (NN / KSPLIT)      // 1024 k per CTA
#define KCH      128                // k per staged chunk
#define NCHUNK   (KRANGE / KCH)     // 8
#define MTILE    64                 // rows per CTA (4 warps x m16)
#define GRID_G   ((NN / MTILE) * KSPLIT)   // 1024
#define TH_G     128

// SMEM layout (per stage): A fp32 [64][PA] + X bf16 [32][PX]
#define PA       132                // float pitch (528 B, 16B multiple)
#define PX       136                // bf16 pitch (272 B, 16B multiple)
#define A_BYTES  (MTILE * PA * 4)   // 33792
#define X_OFF    A_BYTES
#define STAGE    (A_BYTES + 32 * PX * 2)   // 42496
#define SMEM_DYN (2 * STAGE)        // 84992

// Scratch (static device arrays; allocation is forbidden)
__device__ __align__(128) float          g_acc[NN * CH];
__device__ __align__(128) float          g_part[KSPLIT * NN * CH];  // 4 MB
__device__ __align__(128) __nv_bfloat16  g_B[32 * NN];              // [n][k]: n 0-15 hi, 16-31 lo

// ---------------- helpers ----------------
__device__ __forceinline__ uint32_t smem_u32(const void* p) {
    uint32_t a;
    asm("{ .reg .u64 t; cvta.to.shared.u64 t, %1; cvt.u32.u64 %0, t; }" : "=r"(a) : "l"(p));
    return a;
}
__device__ __forceinline__ void cp16(uint32_t dst, const void* src) {
    asm volatile("cp.async.cg.shared.global [%0], [%1], 16;" :: "r"(dst), "l"(src) : "memory");
}
__device__ __forceinline__ void cp_commit() {
    asm volatile("cp.async.commit_group;" ::: "memory");
}
template <int N>
__device__ __forceinline__ void cp_wait() {
    asm volatile("cp.async.wait_group %0;" :: "n"(N) : "memory");
}
// d = { upper: bf16(hi_), lower: bf16(lo) }
__device__ __forceinline__ uint32_t cvt_bf2(float lo, float hi_) {
    uint32_t d;
    asm("cvt.rn.bf16x2.f32 %0, %1, %2;" : "=r"(d) : "f"(hi_), "f"(lo));
    return d;
}
__device__ __forceinline__ void mma16816(float* d, const uint32_t* a, uint32_t b0, uint32_t b1) {
    asm volatile(
        "mma.sync.aligned.m16n8k16.row.col.f32.bf16.bf16.f32 "
        "{%0,%1,%2,%3}, {%4,%5,%6,%7}, {%8,%9}, {%0,%1,%2,%3};"
        : "+f"(d[0]), "+f"(d[1]), "+f"(d[2]), "+f"(d[3])
        : "r"(a[0]), "r"(a[1]), "r"(a[2]), "r"(a[3]), "r"(b0), "r"(b1));
}
// split float2 -> (hi bf16x2, lo bf16x2); low half = first element
__device__ __forceinline__ void split2(float2 v, uint32_t& h, uint32_t& l) {
    h = cvt_bf2(v.x, v.y);
    float r0 = v.x - __uint_as_float(h << 16);
    float r1 = v.y - __uint_as_float(h & 0xffff0000u);
    l = cvt_bf2(r0, r1);
}

// ---------------- kernel: acc = relu(x @ W0) ----------------
__global__ void k_init(const float* __restrict__ x,
                       const float* __restrict__ W,
                       float* __restrict__ acc) {
    __shared__ float sW[CH * CH];
    int t = threadIdx.x;
    sW[t] = W[t];
    __syncthreads();
    int row = blockIdx.x * blockDim.x + t;
    const float4* xr4 = reinterpret_cast<const float4*>(x + (size_t)row * CH);
    float xr[CH];
    float4 v0 = xr4[0], v1 = xr4[1], v2 = xr4[2], v3 = xr4[3];
    xr[0]=v0.x; xr[1]=v0.y; xr[2]=v0.z; xr[3]=v0.w;
    xr[4]=v1.x; xr[5]=v1.y; xr[6]=v1.z; xr[7]=v1.w;
    xr[8]=v2.x; xr[9]=v2.y; xr[10]=v2.z; xr[11]=v2.w;
    xr[12]=v3.x; xr[13]=v3.y; xr[14]=v3.z; xr[15]=v3.w;
    float o[CH];
    #pragma unroll
    for (int c = 0; c < CH; c++) o[c] = 0.f;
    #pragma unroll
    for (int j = 0; j < CH; j++)
        #pragma unroll
        for (int c = 0; c < CH; c++) o[c] += xr[j] * sW[j * CH + c];
    float* ar = acc + (size_t)row * CH;
    #pragma unroll
    for (int c = 0; c < CH; c++) ar[c] = fmaxf(o[c], 0.f);
}

// ---------------- kernel: xp -> g_B (hi/lo bf16, transposed [n][k]) ----------------
__global__ void k_xsplit(const float* __restrict__ xp, __nv_bfloat16* __restrict__ B) {
    int idx = blockIdx.x * blockDim.x + threadIdx.x;
    int m = idx >> 4, c = idx & 15;
    float v = xp[idx];
    __nv_bfloat16 hi = __float2bfloat16_rn(v);
    __nv_bfloat16 lo = __float2bfloat16_rn(v - __bfloat162float(hi));
    B[(size_t)c * NN + m] = hi;
    B[(size_t)(c + 16) * NN + m] = lo;
}

// ---------------- GEMM pass via mma.sync bf16 hi/lo ----------------
// CTA: 64 rows x 1024 k. Warp w owns rows w*16..w*16+15 (m16 fragment).
// part[ks][m][c] = L[m, krange] @ xp[krange, c]
__global__ __launch_bounds__(TH_G, 2)
void k_gemm(const float* __restrict__ L, const __nv_bfloat16* __restrict__ Bg,
            float* __restrict__ part) {
    extern __shared__ __align__(16) char smem[];

    int t = threadIdx.x;
    int w = t >> 5, lane = t & 31;
    int g = lane >> 2, tg = lane & 3;
    int mt = blockIdx.x >> 3, ks = blockIdx.x & 7;
    int m0 = mt * MTILE;
    int k0base = ks * KRANGE;

    uint32_t sb = smem_u32(smem);

    float dA[4] = {0.f, 0.f, 0.f, 0.f};   // output cols 0-7
    float dB[4] = {0.f, 0.f, 0.f, 0.f};   // output cols 8-15

    // ---- staging macro: chunk ci into buffer bs ----
    #define STAGE_CHUNK(ci, bs)                                                   \
    {                                                                             \
        int k0 = k0base + (ci) * KCH;                                             \
        uint32_t sa = sb + (bs) * STAGE;                                          \
        _Pragma("unroll")                                                         \
        for (int it = 0; it < 16; it++) {                                         \
            int slot = it * TH_G + t;                                             \
            int row = slot >> 5, jj = slot & 31;                                  \
            cp16(sa + row * (PA * 4) + jj * 16,                                   \
                 L + (size_t)(m0 + row) * NN + k0 + jj * 4);                      \
        }                                                                         \
        uint32_t sx = sb + (bs) * STAGE + X_OFF;                                  \
        _Pragma("unroll")                                                         \
        for (int it = 0; it < 4; it++) {                                          \
            int slot = it * TH_G + t;                                             \
            int n = slot >> 4, jj = slot & 15;                                    \
            cp16(sx + n * (PX * 2) + jj * 16,                                     \
                 Bg + (size_t)n * NN + k0 + jj * 8);                              \
        }                                                                         \
        cp_commit();                                                              \
    }

    STAGE_CHUNK(0, 0)

    for (int i = 0; i < NCHUNK; i++) {
        if (i + 1 < NCHUNK) { STAGE_CHUNK(i + 1, (i + 1) & 1) }
        if (i + 1 < NCHUNK) cp_wait<1>(); else cp_wait<0>();
        __syncthreads();

        const float* sA = reinterpret_cast<const float*>(smem + (i & 1) * STAGE);
        const __nv_bfloat16* sX =
            reinterpret_cast<const __nv_bfloat16*>(smem + (i & 1) * STAGE + X_OFF);

        const float* sAr0 = sA + (w * 16 + g) * PA;       // row g of warp tile
        const float* sAr1 = sA + (w * 16 + g + 8) * PA;   // row g+8

        #pragma unroll
        for (int kk = 0; kk < KCH / 16; kk++) {           // 8 k16 steps
            int ko = kk * 16 + 2 * tg;

            // A fragment: fp32 -> bf16 hi/lo
            float2 v0 = *reinterpret_cast<const float2*>(sAr0 + ko);       // a0: row g,  cols 2tg
            float2 v1 = *reinterpret_cast<const float2*>(sAr1 + ko);       // a1: row g+8
            float2 v2 = *reinterpret_cast<const float2*>(sAr0 + ko + 8);   // a2: row g,  cols 2tg+8
            float2 v3 = *reinterpret_cast<const float2*>(sAr1 + ko + 8);   // a3: row g+8
            uint32_t ahi[4], alo[4];
            split2(v0, ahi[0], alo[0]);
            split2(v1, ahi[1], alo[1]);
            split2(v2, ahi[2], alo[2]);
            split2(v3, ahi[3], alo[3]);

            // B fragments from sX[n][k]: b0={X[k][n],X[k+1][n]}, b1=k+8
            const __nv_bfloat16* xk = sX + ko;
            uint32_t bh0a = *reinterpret_cast<const uint32_t*>(xk + (g     ) * PX);
            uint32_t bh0b = *reinterpret_cast<const uint32_t*>(xk + (g     ) * PX + 8);
            uint32_t bh8a = *reinterpret_cast<const uint32_t*>(xk + (g +  8) * PX);
            uint32_t bh8b = *reinterpret_cast<const uint32_t*>(xk + (g +  8) * PX + 8);
            uint32_t bl0a = *reinterpret_cast<const uint32_t*>(xk + (g + 16) * PX);
            uint32_t bl0b = *reinterpret_cast<const uint32_t*>(xk + (g + 16) * PX + 8);
            uint32_t bl8a = *reinterpret_cast<const uint32_t*>(xk + (g + 24) * PX);
            uint32_t bl8b = *reinterpret_cast<const uint32_t*>(xk + (g + 24) * PX + 8);

            mma16816(dA, ahi, bh0a, bh0b);   // Ahi @ Xhi  -> cols 0-7
            mma16816(dB, ahi, bh8a, bh8b);   //            -> cols 8-15
            mma16816(dA, ahi, bl0a, bl0b);   // Ahi @ Xlo
            mma16816(dB, ahi, bl8a, bl8b);
            mma16816(dA, alo, bh0a, bh0b);   // Alo @ Xhi
            mma16816(dB, alo, bh8a, bh8b);
        }
        __syncthreads();
    }
    #undef STAGE_CHUNK

    // ---- epilogue: write fp32 partials ----
    float* pp = part + (size_t)ks * NN * CH;
    int m = m0 + w * 16 + g;
    *reinterpret_cast<float2*>(pp + (size_t)m * CH + 2 * tg)           = make_float2(dA[0], dA[1]);
    *reinterpret_cast<float2*>(pp + (size_t)m * CH + 8 + 2 * tg)       = make_float2(dB[0], dB[1]);
    *reinterpret_cast<float2*>(pp + (size_t)(m + 8) * CH + 2 * tg)     = make_float2(dA[2], dA[3]);
    *reinterpret_cast<float2*>(pp + (size_t)(m + 8) * CH + 8 + 2 * tg) = make_float2(dB[2], dB[3]);
}

// ---------------- combine: y = sum(partials); acc += relu(y@Wp); emit next B ----------------
template <bool FINAL>
__global__ void k_combine(const float* __restrict__ part,
                          const float* __restrict__ W,
                          float* __restrict__ acc,
                          __nv_bfloat16* __restrict__ B,
                          float* __restrict__ outp) {
    __shared__ float sy[256];
    __shared__ float sW[CH * CH];
    int t = threadIdx.x;
    sW[t] = W[t];
    int idx = blockIdx.x * 256 + t;           // m*16 + c
    int m = idx >> 4, c = idx & 15;
    float y = 0.f;
    #pragma unroll
    for (int ks = 0; ks < KSPLIT; ks++) y += part[(size_t)ks * NN * CH + idx];
    sy[t] = y;
    if (!FINAL) {
        __nv_bfloat16 hi = __float2bfloat16_rn(y);
        __nv_bfloat16 lo = __float2bfloat16_rn(y - __bfloat162float(hi));
        B[(size_t)c * NN + m] = hi;
        B[(size_t)(c + 16) * NN + m] = lo;
    }
    __syncthreads();
    int rbase = t & 0xF0;
    float s = 0.f;
    #pragma unroll
    for (int j = 0; j < CH; j++) s += sy[rbase + j] * sW[j * CH + c];
    s = fmaxf(s, 0.f);
    if (!FINAL) acc[idx] += s;
    else        outp[idx] = fmaxf(acc[idx] + s, 0.f);
}

extern "C" void kernel_launch(void* const* d_in, const int* in_sizes, int n_in,
                              void* d_out, int out_size) {
    const float* x = (const float*)d_in[0];   // [8192, 16]
    const float* L = (const float*)d_in[1];   // [8192, 8192]
    const float* W = (const float*)d_in[2];   // [5, 16, 16]
    float* out = (float*)d_out;

    void *pa, *pp, *pb;
    cudaGetSymbolAddress(&pa, g_acc);
    cudaGetSymbolAddress(&pp, g_part);
    cudaGetSymbolAddress(&pb, g_B);
    float* acc = (float*)pa;
    float* part = (float*)pp;
    __nv_bfloat16* B = (__nv_bfloat16*)pb;

    cudaFuncSetAttribute(k_gemm, cudaFuncAttributeMaxDynamicSharedMemorySize, SMEM_DYN);

    k_init<<<NN / 256, 256>>>(x, W, acc);                 // acc = relu(x@W0)
    k_xsplit<<<NN * CH / 256, 256>>>(x, B);               // B <- split(x)

    k_gemm<<<GRID_G, TH_G, SMEM_DYN>>>(L, B, part);       // p=1
    k_combine<false><<<NN * CH / 256, 256>>>(part, W + 1 * 256, acc, B, nullptr);
    k_gemm<<<GRID_G, TH_G, SMEM_DYN>>>(L, B, part);       // p=2
    k_combine<false><<<NN * CH / 256, 256>>>(part, W + 2 * 256, acc, B, nullptr);
    k_gemm<<<GRID_G, TH_G, SMEM_DYN>>>(L, B, part);       // p=3
    k_combine<false><<<NN * CH / 256, 256>>>(part, W + 3 * 256, acc, B, nullptr);
    k_gemm<<<GRID_G, TH_G, SMEM_DYN>>>(L, B, part);       // p=4
    k_combine<true ><<<NN * CH / 256, 256>>>(part, W + 4 * 256, acc, B, out);
}

// round 15
// speedup vs baseline: 1.9473x; 1.0709x over previous
#include <cuda_runtime.h>
#include <cuda_bf16.h>
#include <cstdint>

// Problem constants
#define NN       8192
#define CH       16
#define KSPLIT   8
#define KRANGE   (NN / KSPLIT)      // 1024 k per CTA
#define KCH      64                 // k per staged chunk
#define NCHUNK   (KRANGE / KCH)     // 16
#define MTILE    64                 // rows per CTA (4 warps x m16)
#define GRID_G   ((NN / MTILE) * KSPLIT)   // 1024
#define TH_G     128
#define NSTAGE   3

// SMEM layout (per stage): A fp32 [64][PA] + X bf16 [32][PX]
#define PA       68                 // float pitch (272 B, 16B multiple)
#define PX       72                 // bf16 pitch (144 B, 16B multiple)
#define A_BYTES  (MTILE * PA * 4)   // 17408
#define X_OFF    A_BYTES
#define STAGE    (A_BYTES + 32 * PX * 2)   // 22016
#define SMEM_DYN (NSTAGE * STAGE)   // 66048

// Scratch (static device arrays; allocation is forbidden)
__device__ __align__(128) float          g_acc[NN * CH];
__device__ __align__(128) float          g_part[KSPLIT * NN * CH];  // 4 MB
__device__ __align__(128) __nv_bfloat16  g_B[32 * NN];              // [n][k]: n 0-15 hi, 16-31 lo

// ---------------- helpers ----------------
__device__ __forceinline__ uint32_t smem_u32(const void* p) {
    uint32_t a;
    asm("{ .reg .u64 t; cvta.to.shared.u64 t, %1; cvt.u32.u64 %0, t; }" : "=r"(a) : "l"(p));
    return a;
}
__device__ __forceinline__ void cp16(uint32_t dst, const void* src) {
    asm volatile("cp.async.cg.shared.global [%0], [%1], 16;" :: "r"(dst), "l"(src) : "memory");
}
__device__ __forceinline__ void cp_commit() {
    asm volatile("cp.async.commit_group;" ::: "memory");
}
template <int N>
__device__ __forceinline__ void cp_wait() {
    asm volatile("cp.async.wait_group %0;" :: "n"(N) : "memory");
}
// d = { upper: bf16(hi_), lower: bf16(lo) }
__device__ __forceinline__ uint32_t cvt_bf2(float lo, float hi_) {
    uint32_t d;
    asm("cvt.rn.bf16x2.f32 %0, %1, %2;" : "=r"(d) : "f"(hi_), "f"(lo));
    return d;
}
__device__ __forceinline__ void mma16816(float* d, const uint32_t* a, uint32_t b0, uint32_t b1) {
    asm volatile(
        "mma.sync.aligned.m16n8k16.row.col.f32.bf16.bf16.f32 "
        "{%0,%1,%2,%3}, {%4,%5,%6,%7}, {%8,%9}, {%0,%1,%2,%3};"
        : "+f"(d[0]), "+f"(d[1]), "+f"(d[2]), "+f"(d[3])
        : "r"(a[0]), "r"(a[1]), "r"(a[2]), "r"(a[3]), "r"(b0), "r"(b1));
}
// split float2 -> (hi bf16x2, lo bf16x2); low half = first element
__device__ __forceinline__ void split2(float2 v, uint32_t& h, uint32_t& l) {
    h = cvt_bf2(v.x, v.y);
    float r0 = v.x - __uint_as_float(h << 16);
    float r1 = v.y - __uint_as_float(h & 0xffff0000u);
    l = cvt_bf2(r0, r1);
}

// ---------------- kernel: acc = relu(x @ W0) ----------------
__global__ void k_init(const float* __restrict__ x,
                       const float* __restrict__ W,
                       float* __restrict__ acc) {
    __shared__ float sW[CH * CH];
    int t = threadIdx.x;
    sW[t] = W[t];
    __syncthreads();
    int row = blockIdx.x * blockDim.x + t;
    const float4* xr4 = reinterpret_cast<const float4*>(x + (size_t)row * CH);
    float xr[CH];
    float4 v0 = xr4[0], v1 = xr4[1], v2 = xr4[2], v3 = xr4[3];
    xr[0]=v0.x; xr[1]=v0.y; xr[2]=v0.z; xr[3]=v0.w;
    xr[4]=v1.x; xr[5]=v1.y; xr[6]=v1.z; xr[7]=v1.w;
    xr[8]=v2.x; xr[9]=v2.y; xr[10]=v2.z; xr[11]=v2.w;
    xr[12]=v3.x; xr[13]=v3.y; xr[14]=v3.z; xr[15]=v3.w;
    float o[CH];
    #pragma unroll
    for (int c = 0; c < CH; c++) o[c] = 0.f;
    #pragma unroll
    for (int j = 0; j < CH; j++)
        #pragma unroll
        for (int c = 0; c < CH; c++) o[c] += xr[j] * sW[j * CH + c];
    float* ar = acc + (size_t)row * CH;
    #pragma unroll
    for (int c = 0; c < CH; c++) ar[c] = fmaxf(o[c], 0.f);
}

// ---------------- kernel: xp -> g_B (hi/lo bf16, transposed [n][k]) ----------------
__global__ void k_xsplit(const float* __restrict__ xp, __nv_bfloat16* __restrict__ B) {
    int idx = blockIdx.x * blockDim.x + threadIdx.x;
    int m = idx >> 4, c = idx & 15;
    float v = xp[idx];
    __nv_bfloat16 hi = __float2bfloat16_rn(v);
    __nv_bfloat16 lo = __float2bfloat16_rn(v - __bfloat162float(hi));
    B[(size_t)c * NN + m] = hi;
    B[(size_t)(c + 16) * NN + m] = lo;
}

// ---------------- GEMM pass via mma.sync bf16 hi/lo ----------------
// CTA: 64 rows x 1024 k. Warp w owns rows w*16..w*16+15 (m16 fragment).
// 3-stage cp.async ring, prefetch depth 2 chunks.
__global__ __launch_bounds__(TH_G, 3)
void k_gemm(const float* __restrict__ L, const __nv_bfloat16* __restrict__ Bg,
            float* __restrict__ part) {
    extern __shared__ __align__(16) char smem[];

    int t = threadIdx.x;
    int w = t >> 5, lane = t & 31;
    int g = lane >> 2, tg = lane & 3;
    int mt = blockIdx.x >> 3, ks = blockIdx.x & 7;
    int m0 = mt * MTILE;
    int k0base = ks * KRANGE;

    uint32_t sb = smem_u32(smem);

    float dA[4] = {0.f, 0.f, 0.f, 0.f};   // output cols 0-7
    float dB[4] = {0.f, 0.f, 0.f, 0.f};   // output cols 8-15

    // ---- staging macro: chunk ci into ring slot bs ----
    #define STAGE_CHUNK(ci, bs)                                                   \
    {                                                                             \
        int k0 = k0base + (ci) * KCH;                                             \
        uint32_t sa = sb + (bs) * STAGE;                                          \
        _Pragma("unroll")                                                         \
        for (int it = 0; it < 8; it++) {                                          \
            int slot = it * TH_G + t;          /* 0..1023 */                      \
            int row = slot >> 4, jj = slot & 15;                                  \
            cp16(sa + row * (PA * 4) + jj * 16,                                   \
                 L + (size_t)(m0 + row) * NN + k0 + jj * 4);                      \
        }                                                                         \
        uint32_t sx = sb + (bs) * STAGE + X_OFF;                                  \
        _Pragma("unroll")                                                         \
        for (int it = 0; it < 2; it++) {                                          \
            int slot = it * TH_G + t;          /* 0..255 */                       \
            int n = slot >> 3, jj = slot & 7;                                     \
            cp16(sx + n * (PX * 2) + jj * 16,                                     \
                 Bg + (size_t)n * NN + k0 + jj * 8);                              \
        }                                                                         \
        cp_commit();                                                              \
    }

    STAGE_CHUNK(0, 0)
    STAGE_CHUNK(1, 1)

    int slot_c = 0;                       // ring slot of current compute chunk
    int slot_p = 2;                       // ring slot for next prefetch
    for (int i = 0; i < NCHUNK; i++) {
        if (i + 2 < NCHUNK) {
            STAGE_CHUNK(i + 2, slot_p)
            slot_p = (slot_p == NSTAGE - 1) ? 0 : slot_p + 1;
            cp_wait<2>();
        } else if (i + 1 < NCHUNK) {
            cp_wait<1>();
        } else {
            cp_wait<0>();
        }
        __syncthreads();

        const float* sA = reinterpret_cast<const float*>(smem + slot_c * STAGE);
        const __nv_bfloat16* sX =
            reinterpret_cast<const __nv_bfloat16*>(smem + slot_c * STAGE + X_OFF);
        slot_c = (slot_c == NSTAGE - 1) ? 0 : slot_c + 1;

        const float* sAr0 = sA + (w * 16 + g) * PA;       // row g of warp tile
        const float* sAr1 = sA + (w * 16 + g + 8) * PA;   // row g+8

        #pragma unroll
        for (int kk = 0; kk < KCH / 16; kk++) {           // 4 k16 steps
            int ko = kk * 16 + 2 * tg;

            // A fragment: fp32 -> bf16 hi/lo
            float2 v0 = *reinterpret_cast<const float2*>(sAr0 + ko);
            float2 v1 = *reinterpret_cast<const float2*>(sAr1 + ko);
            float2 v2 = *reinterpret_cast<const float2*>(sAr0 + ko + 8);
            float2 v3 = *reinterpret_cast<const float2*>(sAr1 + ko + 8);
            uint32_t ahi[4], alo[4];
            split2(v0, ahi[0], alo[0]);
            split2(v1, ahi[1], alo[1]);
            split2(v2, ahi[2], alo[2]);
            split2(v3, ahi[3], alo[3]);

            // B fragments from sX[n][k]: b0={X[k][n..]}, b1=k+8
            const __nv_bfloat16* xk = sX + ko;
            uint32_t bh0a = *reinterpret_cast<const uint32_t*>(xk + (g     ) * PX);
            uint32_t bh0b = *reinterpret_cast<const uint32_t*>(xk + (g     ) * PX + 8);
            uint32_t bh8a = *reinterpret_cast<const uint32_t*>(xk + (g +  8) * PX);
            uint32_t bh8b = *reinterpret_cast<const uint32_t*>(xk + (g +  8) * PX + 8);
            uint32_t bl0a = *reinterpret_cast<const uint32_t*>(xk + (g + 16) * PX);
            uint32_t bl0b = *reinterpret_cast<const uint32_t*>(xk + (g + 16) * PX + 8);
            uint32_t bl8a = *reinterpret_cast<const uint32_t*>(xk + (g + 24) * PX);
            uint32_t bl8b = *reinterpret_cast<const uint32_t*>(xk + (g + 24) * PX + 8);

            mma16816(dA, ahi, bh0a, bh0b);   // Ahi @ Xhi  -> cols 0-7
            mma16816(dB, ahi, bh8a, bh8b);   //            -> cols 8-15
            mma16816(dA, ahi, bl0a, bl0b);   // Ahi @ Xlo
            mma16816(dB, ahi, bl8a, bl8b);
            mma16816(dA, alo, bh0a, bh0b);   // Alo @ Xhi
            mma16816(dB, alo, bh8a, bh8b);
        }
        __syncthreads();
    }
    #undef STAGE_CHUNK

    // ---- epilogue: write fp32 partials ----
    float* pp = part + (size_t)ks * NN * CH;
    int m = m0 + w * 16 + g;
    *reinterpret_cast<float2*>(pp + (size_t)m * CH + 2 * tg)           = make_float2(dA[0], dA[1]);
    *reinterpret_cast<float2*>(pp + (size_t)m * CH + 8 + 2 * tg)       = make_float2(dB[0], dB[1]);
    *reinterpret_cast<float2*>(pp + (size_t)(m + 8) * CH + 2 * tg)     = make_float2(dA[2], dA[3]);
    *reinterpret_cast<float2*>(pp + (size_t)(m + 8) * CH + 8 + 2 * tg) = make_float2(dB[2], dB[3]);
}

// ---------------- combine: y = sum(partials); acc += relu(y@Wp); emit next B ----------------
template <bool FINAL>
__global__ void k_combine(const float* __restrict__ part,
                          const float* __restrict__ W,
                          float* __restrict__ acc,
                          __nv_bfloat16* __restrict__ B,
                          float* __restrict__ outp) {
    __shared__ float sy[256];
    __shared__ float sW[CH * CH];
    int t = threadIdx.x;
    sW[t] = W[t];
    int idx = blockIdx.x * 256 + t;           // m*16 + c
    int m = idx >> 4, c = idx & 15;
    float y = 0.f;
    #pragma unroll
    for (int ks = 0; ks < KSPLIT; ks++) y += part[(size_t)ks * NN * CH + idx];
    sy[t] = y;
    if (!FINAL) {
        __nv_bfloat16 hi = __float2bfloat16_rn(y);
        __nv_bfloat16 lo = __float2bfloat16_rn(y - __bfloat162float(hi));
        B[(size_t)c * NN + m] = hi;
        B[(size_t)(c + 16) * NN + m] = lo;
    }
    __syncthreads();
    int rbase = t & 0xF0;
    float s = 0.f;
    #pragma unroll
    for (int j = 0; j < CH; j++) s += sy[rbase + j] * sW[j * CH + c];
    s = fmaxf(s, 0.f);
    if (!FINAL) acc[idx] += s;
    else        outp[idx] = fmaxf(acc[idx] + s, 0.f);
}

extern "C" void kernel_launch(void* const* d_in, const int* in_sizes, int n_in,
                              void* d_out, int out_size) {
    const float* x = (const float*)d_in[0];   // [8192, 16]
    const float* L = (const float*)d_in[1];   // [8192, 8192]
    const float* W = (const float*)d_in[2];   // [5, 16, 16]
    float* out = (float*)d_out;

    void *pa, *pp, *pb;
    cudaGetSymbolAddress(&pa, g_acc);
    cudaGetSymbolAddress(&pp, g_part);
    cudaGetSymbolAddress(&pb, g_B);
    float* acc = (float*)pa;
    float* part = (float*)pp;
    __nv_bfloat16* B = (__nv_bfloat16*)pb;

    cudaFuncSetAttribute(k_gemm, cudaFuncAttributeMaxDynamicSharedMemorySize, SMEM_DYN);

    k_init<<<NN / 256, 256>>>(x, W, acc);                 // acc = relu(x@W0)
    k_xsplit<<<NN * CH / 256, 256>>>(x, B);               // B <- split(x)

    k_gemm<<<GRID_G, TH_G, SMEM_DYN>>>(L, B, part);       // p=1
    k_combine<false><<<NN * CH / 256, 256>>>(part, W + 1 * 256, acc, B, nullptr);
    k_gemm<<<GRID_G, TH_G, SMEM_DYN>>>(L, B, part);       // p=2
    k_combine<false><<<NN * CH / 256, 256>>>(part, W + 2 * 256, acc, B, nullptr);
    k_gemm<<<GRID_G, TH_G, SMEM_DYN>>>(L, B, part);       // p=3
    k_combine<false><<<NN * CH / 256, 256>>>(part, W + 3 * 256, acc, B, nullptr);
    k_gemm<<<GRID_G, TH_G, SMEM_DYN>>>(L, B, part);       // p=4
    k_combine<true ><<<NN * CH / 256, 256>>>(part, W + 4 * 256, acc, B, out);
}